// round 13
// baseline (speedup 1.0000x reference)
#include <cuda_runtime.h>

#define B_SZ 65536
#define D_SZ 512
#define V4_PER_ROW (D_SZ / 4)              // 128
#define NC 16
#define NBLOCKS 2048
#define NTHREADS 256
#define WARPS_PER_BLOCK (NTHREADS / 32)    // 8
#define ROWS_PER_WARP 4                    // 2048*8*4 = 65536
#define NPAIR (NC * (NC - 1) / 2)          // 120

#define NTH2 1024                          // finalize block
#define W2 (NTH2 / 32)                     // 32 warps

__device__ float g_partials[NBLOCKS];

// ---- Kernel 1: EXACT R3 streaming body (measured 24.5us standalone) ----
__global__ __launch_bounds__(NTHREADS) void k_center_partials(
    const float4* __restrict__ x,
    const int* __restrict__ y,             // int32 (JAX x64 disabled)
    const float4* __restrict__ centers)
{
    __shared__ float4 sc[NC * V4_PER_ROW];   // 32 KB
    #pragma unroll
    for (int i = 0; i < (NC * V4_PER_ROW) / NTHREADS; i++)
        sc[i * NTHREADS + threadIdx.x] = centers[i * NTHREADS + threadIdx.x];
    __syncthreads();

    const int lane = threadIdx.x & 31;
    const int gw = blockIdx.x * WARPS_PER_BLOCK + (threadIdx.x >> 5);

    float acc = 0.0f;
    #pragma unroll
    for (int r = 0; r < ROWS_PER_WARP; r++) {
        const int row = gw * ROWS_PER_WARP + r;
        const int cls = __ldg(&y[row]) & 15;          // broadcast load
        const float4* __restrict__ xr = x + (size_t)row * V4_PER_ROW;
        const float4* __restrict__ cr = sc + (cls << 7);
        #pragma unroll
        for (int i = 0; i < 4; i++) {
            float4 xv = __ldg(&xr[i * 32 + lane]);    // coalesced 512B
            float4 cv = cr[i * 32 + lane];            // conflict-free LDS.128
            float d0 = xv.x - cv.x;
            float d1 = xv.y - cv.y;
            float d2 = xv.z - cv.z;
            float d3 = xv.w - cv.w;
            acc = fmaf(d0, d0, acc);
            acc = fmaf(d1, d1, acc);
            acc = fmaf(d2, d2, acc);
            acc = fmaf(d3, d3, acc);
        }
    }

    #pragma unroll
    for (int o = 16; o > 0; o >>= 1)
        acc += __shfl_down_sync(0xffffffffu, acc, o);

    __shared__ float ws[WARPS_PER_BLOCK];
    const int wid = threadIdx.x >> 5;
    if (lane == 0) ws[wid] = acc;
    __syncthreads();
    if (wid == 0) {
        float v = (lane < WARPS_PER_BLOCK) ? ws[lane] : 0.0f;
        #pragma unroll
        for (int o = 4; o > 0; o >>= 1)
            v += __shfl_down_sync(0xffffffffu, v, o);
        if (lane == 0) g_partials[blockIdx.x] = v;
    }
}

// ---- Kernel 2: wide finalize (1024 threads, warp-parallel everything) ----
__global__ __launch_bounds__(NTH2) void k_finalize(
    const float4* __restrict__ centers,
    float* __restrict__ out)
{
    __shared__ float4 sc[NC * V4_PER_ROW]; // 32 KB
    __shared__ float norms[NC];
    __shared__ float warp_sum[W2];
    __shared__ float warp_pair[W2];

    const int t = threadIdx.x;
    const int lane = t & 31;
    const int wid = t >> 5;

    // Stage centers: 1024 threads x 2 float4, coalesced
    #pragma unroll
    for (int i = 0; i < (NC * V4_PER_ROW) / NTH2; i++)
        sc[i * NTH2 + t] = centers[i * NTH2 + t];

    // Partials (2048 floats, L2-hot): 2 loads/thread, warp reduce (fixed order)
    float s = g_partials[t] + g_partials[t + NTH2];
    #pragma unroll
    for (int o = 16; o > 0; o >>= 1)
        s += __shfl_down_sync(0xffffffffu, s, o);
    if (lane == 0) warp_sum[wid] = s;
    __syncthreads();

    // Norms: one warp per class row (warps 0..15)
    if (wid < NC) {
        const float4* cr = sc + (wid << 7);
        float ns = 0.0f;
        #pragma unroll
        for (int i = 0; i < 4; i++) {
            float4 v = cr[i * 32 + lane];
            ns += v.x * v.x + v.y * v.y + v.z * v.z + v.w * v.w;
        }
        #pragma unroll
        for (int o = 16; o > 0; o >>= 1)
            ns += __shfl_down_sync(0xffffffffu, ns, o);
        if (lane == 0) norms[wid] = sqrtf(ns);
    }
    __syncthreads();

    // Pairs: 4 per warp over warps 0..29 (fixed order within each warp)
    float psum = 0.0f;
    if (wid < 30) {
        #pragma unroll
        for (int pp = 0; pp < 4; pp++) {
            const int p = wid * 4 + pp;
            int j = 0, rem = p;
            while (rem >= NC - 1 - j) { rem -= NC - 1 - j; j++; }
            const int k = j + 1 + rem;
            const float4* cj = sc + (j << 7);
            const float4* ck = sc + (k << 7);
            float dot = 0.0f;
            #pragma unroll
            for (int i = 0; i < 4; i++) {
                float4 a = cj[i * 32 + lane];
                float4 b = ck[i * 32 + lane];
                dot += a.x * b.x + a.y * b.y + a.z * b.z + a.w * b.w;
            }
            #pragma unroll
            for (int o = 16; o > 0; o >>= 1)
                dot += __shfl_down_sync(0xffffffffu, dot, o);
            if (lane == 0)
                psum += dot / (norms[j] * norms[k] + 1e-9f) + 1.0f;
        }
    }
    if (lane == 0) warp_pair[wid] = (wid < 30) ? psum : 0.0f;
    __syncthreads();

    // Final: warp 0 folds the 32 warp sums (fixed order via lane-indexed shfl)
    if (wid == 0) {
        float tot = warp_sum[lane];
        float isl = warp_pair[lane];
        #pragma unroll
        for (int o = 16; o > 0; o >>= 1) {
            tot += __shfl_down_sync(0xffffffffu, tot, o);
            isl += __shfl_down_sync(0xffffffffu, isl, o);
        }
        if (lane == 0) {
            // SCALE = 1, LAMDA = 1, LAMDA1 = 10
            float loss_center = 0.5f * tot * (1.0f / (float)B_SZ);
            out[0] = loss_center + 10.0f * isl;
        }
    }
}

extern "C" void kernel_launch(void* const* d_in, const int* in_sizes, int n_in,
                              void* d_out, int out_size)
{
    // Identify inputs by element count (robust to ordering):
    //   output_features: 65536*512 = 33554432
    //   y_truth:         65536
    //   feature_centers: 16*512   = 8192
    const float4* x = nullptr;
    const int* y = nullptr;
    const float4* centers = nullptr;
    for (int i = 0; i < n_in; i++) {
        if (in_sizes[i] == 33554432)      x = (const float4*)d_in[i];
        else if (in_sizes[i] == 65536)    y = (const int*)d_in[i];
        else if (in_sizes[i] == 8192)     centers = (const float4*)d_in[i];
    }
    float* out = (float*)d_out;

    k_center_partials<<<NBLOCKS, NTHREADS>>>(x, y, centers);
    k_finalize<<<1, NTH2>>>(centers, out);
}

// round 14
// speedup vs baseline: 1.1846x; 1.1846x over previous
#include <cuda_runtime.h>

#define B_SZ 65536
#define D_SZ 512
#define V4_PER_ROW (D_SZ / 4)              // 128
#define NC 16
#define NBLOCKS 2048
#define NTHREADS 256
#define WARPS_PER_BLOCK (NTHREADS / 32)    // 8
#define ROWS_PER_WARP 4                    // 2048*8*4 = 65536
#define NPAIR (NC * (NC - 1) / 2)          // 120
#define PAIRS_PER_WARP (NPAIR / WARPS_PER_BLOCK)  // 15

__device__ float g_partials[NBLOCKS];
__device__ unsigned int g_ticket = 0;      // atomicInc wraps to 0 -> graph-replay safe

__global__ __launch_bounds__(NTHREADS) void k_island_fused(
    const float4* __restrict__ x,
    const int* __restrict__ y,             // int32 (JAX x64 disabled)
    const float4* __restrict__ centers,
    float* __restrict__ out)
{
    __shared__ float4 sc[NC * V4_PER_ROW]; // 32 KB center cache (proven R8 config)
    __shared__ float ws[WARPS_PER_BLOCK];
    __shared__ float norms[NC];
    __shared__ float warp_pair[WARPS_PER_BLOCK];
    __shared__ unsigned int s_ticket;

    const int t = threadIdx.x;
    const int lane = t & 31;
    const int wid = t >> 5;

    #pragma unroll
    for (int i = 0; i < (NC * V4_PER_ROW) / NTHREADS; i++)
        sc[i * NTHREADS + t] = centers[i * NTHREADS + t];
    __syncthreads();

    // ---- Phase 1: R8 streaming body; x loads marked streaming (evict-first) ----
    const int gw = blockIdx.x * WARPS_PER_BLOCK + wid;

    float acc = 0.0f;
    #pragma unroll
    for (int r = 0; r < ROWS_PER_WARP; r++) {
        const int row = gw * ROWS_PER_WARP + r;
        const int cls = __ldg(&y[row]) & 15;          // broadcast load
        const float4* __restrict__ xr = x + (size_t)row * V4_PER_ROW;
        const float4* __restrict__ cr = sc + (cls << 7);
        #pragma unroll
        for (int i = 0; i < 4; i++) {
            float4 xv = __ldcs(&xr[i * 32 + lane]);   // read-once: streaming hint
            float4 cv = cr[i * 32 + lane];            // conflict-free LDS.128
            float d0 = xv.x - cv.x;
            float d1 = xv.y - cv.y;
            float d2 = xv.z - cv.z;
            float d3 = xv.w - cv.w;
            acc = fmaf(d0, d0, acc);
            acc = fmaf(d1, d1, acc);
            acc = fmaf(d2, d2, acc);
            acc = fmaf(d3, d3, acc);
        }
    }

    #pragma unroll
    for (int o = 16; o > 0; o >>= 1)
        acc += __shfl_down_sync(0xffffffffu, acc, o);
    if (lane == 0) ws[wid] = acc;
    __syncthreads();
    if (t == 0) {
        float v = 0.f;
        #pragma unroll
        for (int w = 0; w < WARPS_PER_BLOCK; w++) v += ws[w];
        g_partials[blockIdx.x] = v;
        __threadfence();
        s_ticket = atomicInc(&g_ticket, NBLOCKS - 1);
    }
    __syncthreads();
    if (s_ticket != NBLOCKS - 1)
        return;                                       // not the last block

    // ---- Phase 2 (last block only): final reduce + island term ----
    float s = 0.0f;
    #pragma unroll
    for (int i = 0; i < NBLOCKS / NTHREADS; i++)
        s += g_partials[i * NTHREADS + t];
    #pragma unroll
    for (int o = 16; o > 0; o >>= 1)
        s += __shfl_down_sync(0xffffffffu, s, o);
    if (lane == 0) ws[wid] = s;

    // Norms: warp-per-2-rows (centers still resident in sc)
    #pragma unroll
    for (int r = 0; r < 2; r++) {
        const int row = wid * 2 + r;
        const float4* cr = sc + (row << 7);
        float ns = 0.0f;
        #pragma unroll
        for (int i = 0; i < 4; i++) {
            float4 v = cr[i * 32 + lane];
            ns += v.x * v.x + v.y * v.y + v.z * v.z + v.w * v.w;
        }
        #pragma unroll
        for (int o = 16; o > 0; o >>= 1)
            ns += __shfl_down_sync(0xffffffffu, ns, o);
        if (lane == 0) norms[row] = sqrtf(ns);
    }
    __syncthreads();

    // Pairs: 15 per warp, fixed order
    float psum = 0.0f;
    #pragma unroll
    for (int pp = 0; pp < PAIRS_PER_WARP; pp++) {
        const int p = wid * PAIRS_PER_WARP + pp;
        int j = 0, rem = p;
        while (rem >= NC - 1 - j) { rem -= NC - 1 - j; j++; }
        const int k = j + 1 + rem;
        const float4* cj = sc + (j << 7);
        const float4* ck = sc + (k << 7);
        float dot = 0.0f;
        #pragma unroll
        for (int i = 0; i < 4; i++) {
            float4 a = cj[i * 32 + lane];
            float4 b = ck[i * 32 + lane];
            dot += a.x * b.x + a.y * b.y + a.z * b.z + a.w * b.w;
        }
        #pragma unroll
        for (int o = 16; o > 0; o >>= 1)
            dot += __shfl_down_sync(0xffffffffu, dot, o);
        if (lane == 0)
            psum += dot / (norms[j] * norms[k] + 1e-9f) + 1.0f;
    }
    if (lane == 0) warp_pair[wid] = psum;
    __syncthreads();

    if (t == 0) {
        float total = 0.0f;
        float island = 0.0f;
        #pragma unroll
        for (int w = 0; w < WARPS_PER_BLOCK; w++) {
            total += ws[w];
            island += warp_pair[w];
        }
        // SCALE = 1, LAMDA = 1, LAMDA1 = 10
        float loss_center = 0.5f * total * (1.0f / (float)B_SZ);
        out[0] = loss_center + 10.0f * island;
    }
}

extern "C" void kernel_launch(void* const* d_in, const int* in_sizes, int n_in,
                              void* d_out, int out_size)
{
    // Identify inputs by element count (robust to ordering):
    //   output_features: 65536*512 = 33554432
    //   y_truth:         65536
    //   feature_centers: 16*512   = 8192
    const float4* x = nullptr;
    const int* y = nullptr;
    const float4* centers = nullptr;
    for (int i = 0; i < n_in; i++) {
        if (in_sizes[i] == 33554432)      x = (const float4*)d_in[i];
        else if (in_sizes[i] == 65536)    y = (const int*)d_in[i];
        else if (in_sizes[i] == 8192)     centers = (const float4*)d_in[i];
    }
    float* out = (float*)d_out;

    k_island_fused<<<NBLOCKS, NTHREADS>>>(x, y, centers, out);
}